// round 11
// baseline (speedup 1.0000x reference)
#include <cuda_runtime.h>
#include <cuda_fp16.h>
#include <cstdint>

// Problem dims
#define T_DIM 8192
#define K_DIM 4096
#define O_DIM 11008
#define QB    64

// Two-term split: A row = [xh(4096) | xl(4096)], B row = [wh(4096) | wl(4096)]
#define AK 8192

// GEMM tiling: 128x256 CTA tile, K64 slab per stage, 3-product schedule K=192 blocks
#define BM 128
#define BN 256
#define BK 64
#define NSTAGE 3
#define NTHREADS 256
#define KBLKS 192                   // 64 (xh*wh) + 64 (xh*wl) + 64 (xl*wh)

#define A_ST_BYTES (BM * 128)       // 16384
#define B_ST_BYTES (BN * 128)       // 32768
#define STAGE_BYTES (A_ST_BYTES + B_ST_BYTES)  // 49152
#define SMEM_TOTAL (NSTAGE * STAGE_BYTES)       // 147456

// fp16 scratch, row-major (R3-proven layout)
__device__ __align__(16) __half g_a[(size_t)T_DIM * AK];   // [xh | xl]
__device__ __align__(16) __half g_b[(size_t)O_DIM * AK];   // [wh | wl]

// ---------------------------------------------------------------- helpers
__device__ __forceinline__ uint32_t smem_u32(const void* p) {
    uint32_t a;
    asm("{ .reg .u64 t; cvta.to.shared.u64 t, %1; cvt.u32.u64 %0, t; }" : "=r"(a) : "l"(p));
    return a;
}
__device__ __forceinline__ uint32_t swz(uint32_t off) { return off ^ ((off >> 3) & 0x70); }

__device__ __forceinline__ void cp_async16(uint32_t dst, const void* src) {
    asm volatile("cp.async.cg.shared.global [%0], [%1], 16;\n" :: "r"(dst), "l"(src));
}
__device__ __forceinline__ void cp_commit() { asm volatile("cp.async.commit_group;\n" ::: "memory"); }
template <int N>
__device__ __forceinline__ void cp_wait() { asm volatile("cp.async.wait_group %0;\n" :: "n"(N) : "memory"); }

#define LDSM_X4(r, addr) \
    asm volatile("ldmatrix.sync.aligned.m8n8.x4.shared.b16 {%0,%1,%2,%3}, [%4];" \
        : "=r"((r)[0]), "=r"((r)[1]), "=r"((r)[2]), "=r"((r)[3]) : "r"(addr))

#define MMA16816(c, a, b0, b1) \
    asm volatile("mma.sync.aligned.m16n8k16.row.col.f32.f16.f16.f32 " \
        "{%0,%1,%2,%3}, {%4,%5,%6,%7}, {%8,%9}, {%0,%1,%2,%3};" \
        : "+f"((c)[0]), "+f"((c)[1]), "+f"((c)[2]), "+f"((c)[3]) \
        : "r"((a)[0]), "r"((a)[1]), "r"((a)[2]), "r"((a)[3]), "r"(b0), "r"(b1))

// ---------------------------------------------------------------- prep kernels (R3-proven)
__global__ void __launch_bounds__(256) xsplit_kernel(const float* __restrict__ x) {
    const size_t n4 = (size_t)T_DIM * K_DIM / 4;
    for (size_t v = (size_t)blockIdx.x * blockDim.x + threadIdx.x; v < n4;
         v += (size_t)gridDim.x * blockDim.x) {
        size_t e = v * 4;
        size_t t = e >> 12;
        size_t i = e & 4095;
        float4 f = reinterpret_cast<const float4*>(x)[v];
        __half h0 = __float2half_rn(f.x), h1 = __float2half_rn(f.y);
        __half h2 = __float2half_rn(f.z), h3 = __float2half_rn(f.w);
        __half l0 = __float2half_rn(f.x - __half2float(h0));
        __half l1 = __float2half_rn(f.y - __half2float(h1));
        __half l2 = __float2half_rn(f.z - __half2float(h2));
        __half l3 = __float2half_rn(f.w - __half2float(h3));
        __half2 hi0 = __halves2half2(h0, h1), hi1 = __halves2half2(h2, h3);
        __half2 lo0 = __halves2half2(l0, l1), lo1 = __halves2half2(l2, l3);
        uint2 uh, ul;
        uh.x = *reinterpret_cast<uint32_t*>(&hi0); uh.y = *reinterpret_cast<uint32_t*>(&hi1);
        ul.x = *reinterpret_cast<uint32_t*>(&lo0); ul.y = *reinterpret_cast<uint32_t*>(&lo1);
        *reinterpret_cast<uint2*>(g_a + t * AK + i) = uh;
        *reinterpret_cast<uint2*>(g_a + t * AK + K_DIM + i) = ul;
    }
}

__global__ void __launch_bounds__(256) wsplit_kernel(const float* __restrict__ w,
                                                     const float* __restrict__ s) {
    const size_t n4 = (size_t)O_DIM * K_DIM / 4;
    const int SCOLS = K_DIM / QB;  // 64
    for (size_t v = (size_t)blockIdx.x * blockDim.x + threadIdx.x; v < n4;
         v += (size_t)gridDim.x * blockDim.x) {
        size_t e = v * 4;
        size_t o = e >> 12;
        size_t i = e & 4095;
        float sc = s[(o >> 6) * SCOLS + (i >> 6)];
        float4 f = reinterpret_cast<const float4*>(w)[v];
        float d0 = f.x * sc, d1 = f.y * sc, d2 = f.z * sc, d3 = f.w * sc;
        __half h0 = __float2half_rn(d0), h1 = __float2half_rn(d1);
        __half h2 = __float2half_rn(d2), h3 = __float2half_rn(d3);
        __half l0 = __float2half_rn(d0 - __half2float(h0));
        __half l1 = __float2half_rn(d1 - __half2float(h1));
        __half l2 = __float2half_rn(d2 - __half2float(h2));
        __half l3 = __float2half_rn(d3 - __half2float(h3));
        __half2 hi0 = __halves2half2(h0, h1), hi1 = __halves2half2(h2, h3);
        __half2 lo0 = __halves2half2(l0, l1), lo1 = __halves2half2(l2, l3);
        uint2 uh, ul;
        uh.x = *reinterpret_cast<uint32_t*>(&hi0); uh.y = *reinterpret_cast<uint32_t*>(&hi1);
        ul.x = *reinterpret_cast<uint32_t*>(&lo0); ul.y = *reinterpret_cast<uint32_t*>(&lo1);
        *reinterpret_cast<uint2*>(g_b + o * AK + i) = uh;
        *reinterpret_cast<uint2*>(g_b + o * AK + K_DIM + i) = ul;
    }
}

// Per-stage K-block remap (3-product schedule):
//   kb in [0,64):    xh (A col kb)      * wh (B col kb)
//   kb in [64,128):  xh (A col kb-64)   * wl (B col kb)       [wl at +4096]
//   kb in [128,192): xl (A col kb-64)   * wh (B col kb-128)   [xl at +4096]
__device__ __forceinline__ int a_kblk(int kb) { return (kb < 128) ? (kb & 63) : (kb - 64); }
__device__ __forceinline__ int b_kblk(int kb) { return (kb < 128) ? kb : (kb - 128); }

// ---------------------------------------------------------------- GEMM
// 8 warps (256 thr) in 2(m) x 4(n); warp tile 64x64; fragment double-buffer across ks.
// Loads: R3's computed-swizzle cp.async from row-major gmem (the proven-fast path).
__global__ void __launch_bounds__(NTHREADS, 1) gemm_kernel(float* __restrict__ out) {
    extern __shared__ char smem[];
    const uint32_t sbase = smem_u32(smem);
    const int tid = threadIdx.x;
    const int wid = tid >> 5;
    const int lid = tid & 31;

    const int t0 = blockIdx.x * BM;   // m fastest-varying (B-tile L2 reuse)
    const int o0 = blockIdx.y * BN;

    const __half* Ag = g_a + (size_t)t0 * AK;
    const __half* Bg = g_b + (size_t)o0 * AK;

    auto load_stage = [&](int st, int kb) {
        if (kb < KBLKS) {
            const uint32_t abase = sbase + st * STAGE_BYTES;
            const uint32_t bbase = abase + A_ST_BYTES;
            const int ak = a_kblk(kb) * BK;
            const int bk = b_kblk(kb) * BK;
            #pragma unroll
            for (int c = tid; c < (BM + BN) * 8; c += NTHREADS) {
                int row = c >> 3, ch = c & 7;
                if (row < BM)
                    cp_async16(abase + swz(row * 128 + ch * 16),
                               Ag + (size_t)row * AK + ak + ch * 8);
                else
                    cp_async16(bbase + swz((row - BM) * 128 + ch * 16),
                               Bg + (size_t)(row - BM) * AK + bk + ch * 8);
            }
        }
        cp_commit();
    };

    const int warp_m = wid & 1;
    const int warp_n = wid >> 1;           // 0..3
    const int m_off = warp_m * 64;
    const int n_off = warp_n * 64;
    const int lrow = lid & 15;
    const int lc16 = lid >> 4;

    uint32_t preA[4], preB[4];
    #pragma unroll
    for (int mi = 0; mi < 4; mi++)
        preA[mi] = swz((uint32_t)((m_off + mi * 16 + lrow) * 128 + lc16 * 16));
    #pragma unroll
    for (int nj = 0; nj < 4; nj++)
        preB[nj] = swz((uint32_t)((n_off + nj * 16 + lrow) * 128 + lc16 * 16));

    float acc[4][8][4];
    #pragma unroll
    for (int mi = 0; mi < 4; mi++)
        #pragma unroll
        for (int ni = 0; ni < 8; ni++)
            #pragma unroll
            for (int q = 0; q < 4; q++) acc[mi][ni][q] = 0.f;

    uint32_t af[2][4][4], bf[2][4][4];

    load_stage(0, 0);
    load_stage(1, 1);

    for (int kb = 0; kb < KBLKS; kb++) {
        cp_wait<1>();
        __syncthreads();
        load_stage((kb + 2) % NSTAGE, kb + 2);

        const uint32_t sA = sbase + (kb % NSTAGE) * STAGE_BYTES;
        const uint32_t sB = sA + A_ST_BYTES;

        // prime ks=0 fragments
        #pragma unroll
        for (int mi = 0; mi < 4; mi++) LDSM_X4(af[0][mi], sA + preA[mi]);
        #pragma unroll
        for (int nj = 0; nj < 4; nj++) LDSM_X4(bf[0][nj], sB + preB[nj]);

        #pragma unroll
        for (int ks = 0; ks < 4; ks++) {
            const int cur = ks & 1;
            if (ks < 3) {                       // prefetch ks+1 while computing ks
                const uint32_t xk = (uint32_t)(ks + 1) * 32;
                const int nxt = cur ^ 1;
                #pragma unroll
                for (int mi = 0; mi < 4; mi++) LDSM_X4(af[nxt][mi], sA + (preA[mi] ^ xk));
                #pragma unroll
                for (int nj = 0; nj < 4; nj++) LDSM_X4(bf[nxt][nj], sB + (preB[nj] ^ xk));
            }
            #pragma unroll
            for (int mi = 0; mi < 4; mi++)
                #pragma unroll
                for (int ni = 0; ni < 8; ni++)
                    MMA16816(acc[mi][ni], af[cur][mi],
                             bf[cur][ni >> 1][ni & 1], bf[cur][ni >> 1][2 + (ni & 1)]);
        }
    }

    // Epilogue: direct register -> gmem float2 stores
    #pragma unroll
    for (int mi = 0; mi < 4; mi++) {
        const int r0 = t0 + m_off + mi * 16 + (lid >> 2);
        #pragma unroll
        for (int ni = 0; ni < 8; ni++) {
            const int c = o0 + n_off + ni * 8 + ((lid & 3) << 1);
            *reinterpret_cast<float2*>(out + (size_t)r0 * O_DIM + c) =
                make_float2(acc[mi][ni][0], acc[mi][ni][1]);
            *reinterpret_cast<float2*>(out + (size_t)(r0 + 8) * O_DIM + c) =
                make_float2(acc[mi][ni][2], acc[mi][ni][3]);
        }
    }
}

// ---------------------------------------------------------------- launch
extern "C" void kernel_launch(void* const* d_in, const int* in_sizes, int n_in,
                              void* d_out, int out_size) {
    (void)in_sizes; (void)n_in; (void)out_size;
    const float* x = (const float*)d_in[0];
    const float* w = (const float*)d_in[1];
    const float* s = (const float*)d_in[2];
    float* out = (float*)d_out;

    xsplit_kernel<<<2048, 256>>>(x);
    wsplit_kernel<<<2048, 256>>>(w, s);

    cudaFuncSetAttribute(gemm_kernel, cudaFuncAttributeMaxDynamicSharedMemorySize, SMEM_TOTAL);
    dim3 grid(T_DIM / BM, O_DIM / BN);  // (64, 43), m fastest
    gemm_kernel<<<grid, NTHREADS, SMEM_TOTAL>>>(out);
}